// round 1
// baseline (speedup 1.0000x reference)
#include <cuda_runtime.h>
#include <cuda_bf16.h>

// out[b,h,i,j] = mask[b,h,i,j] - |slope(h) * (i - j)|
// B=2, NH=16, L=2048, H=64 (q/k/v unused for values).
// NH=16 is a power of two -> slope[h] = 2^(-0.5*(h+1)).
//
// Pure HBM-bound elementwise: 512 MiB in + 512 MiB out.
// One block per row (b,h,i): 512 threads x float4 = 2048 elements.

__global__ __launch_bounds__(512) void alibi_kernel(
    const float* __restrict__ mask,
    float* __restrict__ out,
    int NH, int L)
{
    // row index r in [0, B*NH*L)
    const int r = blockIdx.x;
    const int i = r % L;              // query position
    const int h = (r / L) % NH;       // head

    // slope = 2^(-0.5*(h+1))  (power-of-two head count)
    const float slope = exp2f(-0.5f * (float)(h + 1));

    const long long base = (long long)r * (long long)L;
    const float4* __restrict__ m4 = (const float4*)(mask + base);
    float4* __restrict__ o4 = (float4*)(out + base);

    const int t = threadIdx.x;        // 0..511
    const int j0 = t * 4;

    float4 m = m4[t];
    const float fi = (float)i;
    // bias = slope * |i - j|
    float b0 = slope * fabsf(fi - (float)(j0 + 0));
    float b1 = slope * fabsf(fi - (float)(j0 + 1));
    float b2 = slope * fabsf(fi - (float)(j0 + 2));
    float b3 = slope * fabsf(fi - (float)(j0 + 3));

    float4 o;
    o.x = m.x - b0;
    o.y = m.y - b1;
    o.z = m.z - b2;
    o.w = m.w - b3;
    o4[t] = o;
}

extern "C" void kernel_launch(void* const* d_in, const int* in_sizes, int n_in,
                              void* d_out, int out_size)
{
    // inputs: mask (B,NH,L,L) fp32; q,k,v (unused for values)
    const float* mask = (const float*)d_in[0];
    float* out = (float*)d_out;

    // Shapes fixed by the problem: B=2, NH=16, L=2048.
    // Derive defensively from sizes: q is (B, L, NH, H) with H=64.
    const int NH = 16;
    const int L  = 2048;
    const long long total = (long long)in_sizes[0];     // B*NH*L*L
    const int rows = (int)(total / L);                  // B*NH*L = 65536

    alibi_kernel<<<rows, 512>>>(mask, out, NH, L);
}

// round 2
// speedup vs baseline: 1.0574x; 1.0574x over previous
#include <cuda_runtime.h>
#include <cuda_bf16.h>

// out[b,h,i,j] = mask[b,h,i,j] - |slope(h) * (i - j)|
// B=2, NH=16, L=2048. HBM-bound: 512 MiB read + 512 MiB write.
//
// R2: 4 rows per block -> 4 independent LDG.128 per thread (MLP_p1=4),
// amortized index math, 1/4 the blocks.

#define ROWS_PER_BLK 4

__global__ __launch_bounds__(512) void alibi_kernel(
    const float* __restrict__ mask,
    float* __restrict__ out,
    int L)
{
    // Base row for this block; all 4 rows share (b,h) since L % 4 == 0.
    const int rb = blockIdx.x * ROWS_PER_BLK;
    const int i0 = rb & (2048 - 1);          // rb % L, L=2048
    const int h  = (rb >> 11) & 15;          // (rb / L) % NH

    // slope = 2^(-0.5*(h+1))  (NH=16 is a power of two)
    const float slope = exp2f(-0.5f * (float)(h + 1));

    const int t  = threadIdx.x;              // 0..511
    const int j0 = t * 4;

    const long long base = (long long)rb * (long long)L;
    const float4* __restrict__ m4 = (const float4*)(mask + base);
    float4*       __restrict__ o4 = (float4*)(out + base);

    // Front-batched independent loads (rows are L/4 float4 apart = 512).
    float4 m[ROWS_PER_BLK];
    #pragma unroll
    for (int r = 0; r < ROWS_PER_BLK; r++)
        m[r] = m4[r * 512 + t];

    #pragma unroll
    for (int r = 0; r < ROWS_PER_BLK; r++) {
        const float fi = (float)(i0 + r);
        float4 o;
        o.x = m[r].x - slope * fabsf(fi - (float)(j0 + 0));
        o.y = m[r].y - slope * fabsf(fi - (float)(j0 + 1));
        o.z = m[r].z - slope * fabsf(fi - (float)(j0 + 2));
        o.w = m[r].w - slope * fabsf(fi - (float)(j0 + 3));
        o4[r * 512 + t] = o;
    }
}

extern "C" void kernel_launch(void* const* d_in, const int* in_sizes, int n_in,
                              void* d_out, int out_size)
{
    const float* mask = (const float*)d_in[0];
    float* out = (float*)d_out;

    const int L = 2048;
    const long long total = (long long)in_sizes[0];        // B*NH*L*L
    const int rows = (int)(total / L);                     // 65536
    const int blocks = rows / ROWS_PER_BLK;                // 16384

    alibi_kernel<<<blocks, 512>>>(mask, out, L);
}

// round 3
// speedup vs baseline: 1.0634x; 1.0057x over previous
#include <cuda_runtime.h>
#include <cuda_bf16.h>

// out[b,h,i,j] = mask[b,h,i,j] - |slope(h) * (i - j)|
// B=2, NH=16, L=2048. HBM-bound: 512 MiB read + 512 MiB write.
//
// R3: 8 rows per block (MLP_p1=8) + streaming cache hints (__ldcs/__stcs)
// to keep the zero-reuse stream from thrashing L2 sets.

#define ROWS_PER_BLK 8

__global__ __launch_bounds__(512) void alibi_kernel(
    const float* __restrict__ mask,
    float* __restrict__ out,
    int L)
{
    // Base row for this block; all 8 rows share (b,h) since L % 8 == 0.
    const int rb = blockIdx.x * ROWS_PER_BLK;
    const int i0 = rb & (2048 - 1);          // rb % L, L=2048
    const int h  = (rb >> 11) & 15;          // (rb / L) % NH

    // slope = 2^(-0.5*(h+1))  (NH=16 is a power of two)
    const float slope = exp2f(-0.5f * (float)(h + 1));

    const int t  = threadIdx.x;              // 0..511
    const int j0 = t * 4;

    const long long base = (long long)rb * (long long)L;
    const float4* __restrict__ m4 = (const float4*)(mask + base);
    float4*       __restrict__ o4 = (float4*)(out + base);

    // Front-batched independent streaming loads (rows are 512 float4 apart).
    float4 m[ROWS_PER_BLK];
    #pragma unroll
    for (int r = 0; r < ROWS_PER_BLK; r++)
        m[r] = __ldcs(&m4[r * 512 + t]);

    // Bias for row i0 at columns j0..j0+3; subsequent rows shift by +slope
    // in |.| argument — compute each directly (ALU is nowhere near binding).
    #pragma unroll
    for (int r = 0; r < ROWS_PER_BLK; r++) {
        const float fi = (float)(i0 + r);
        float4 o;
        o.x = m[r].x - slope * fabsf(fi - (float)(j0 + 0));
        o.y = m[r].y - slope * fabsf(fi - (float)(j0 + 1));
        o.z = m[r].z - slope * fabsf(fi - (float)(j0 + 2));
        o.w = m[r].w - slope * fabsf(fi - (float)(j0 + 3));
        __stcs(&o4[r * 512 + t], o);
    }
}

extern "C" void kernel_launch(void* const* d_in, const int* in_sizes, int n_in,
                              void* d_out, int out_size)
{
    const float* mask = (const float*)d_in[0];
    float* out = (float*)d_out;

    const int L = 2048;
    const long long total = (long long)in_sizes[0];        // B*NH*L*L
    const int rows = (int)(total / L);                     // 65536
    const int blocks = rows / ROWS_PER_BLK;                // 8192

    alibi_kernel<<<blocks, 512>>>(mask, out, L);
}